// round 3
// baseline (speedup 1.0000x reference)
#include <cuda_runtime.h>
#include <cuda_bf16.h>
#include <cstdint>

#define D      64
#define NMAX   100000

// Scratch (allocation-free rule: __device__ globals)
__device__ __align__(16) float4 g_hs[(size_t)NMAX * (D / 4)];  // h * dinv(src-side pre-scale)
__device__ float g_dinv[NMAX];
__device__ int   g_deg[NMAX];
__device__ int   g_mode;   // 0 = edge_index is int64, 1 = int32

// ---------------------------------------------------------------------------
// Read edge index robustly (dtype decided at runtime by k_detect)
__device__ __forceinline__ int edge_at(const void* ei, int mode, size_t i, int n) {
    long long v;
    if (mode == 0) v = ((const long long*)ei)[i];
    else           v = (long long)((const int*)ei)[i];
    // clamp: mis-detection gives wrong answers (diagnosable) instead of a trap
    if (v < 0)  v = 0;
    if (v >= n) v = n - 1;
    return (int)v;
}

// K_detect: decide int64 vs int32 interpretation of edge_index.
__global__ void k_detect(const void* ei, int E, int n) {
    if (blockIdx.x == 0 && threadIdx.x == 0) {
        const long long* p64 = (const long long*)ei;
        int lim = E < 1024 ? E : 1024;
        int ok64 = 1;
        for (int i = 0; i < lim; i++) {
            long long v = p64[i];
            if (v < 0 || v >= (long long)n) { ok64 = 0; break; }
        }
        g_mode = ok64 ? 0 : 1;
    }
}

// K0: zero degree counters
__global__ void k_zero_deg(int n) {
    int i = blockIdx.x * blockDim.x + threadIdx.x;
    if (i < n) g_deg[i] = 0;
}

// K1: degree count over destinations (self-loop +1 added later)
__global__ void k_degree(const void* __restrict__ ei, int E, int n) {
    int e = blockIdx.x * blockDim.x + threadIdx.x;
    if (e < E) {
        int mode = g_mode;
        int dst = edge_at(ei, mode, (size_t)E + e, n);
        atomicAdd(&g_deg[dst], 1);
    }
}

// K2: dinv = rsqrt(deg + 1)   (+1 = self-loop)
__global__ void k_dinv(int n) {
    int i = blockIdx.x * blockDim.x + threadIdx.x;
    if (i < n) g_dinv[i] = rsqrtf((float)(g_deg[i] + 1));
}

// ---------------------------------------------------------------------------
// K3: fused dual GEMM + out init.
//   hs[n]  = (x[n] @ Wg) * dinv[n]
//   out[n] = pos[n] @ Wp + b_pos + b_gcn + hs[n]*dinv[n]   (self-loop term)
__global__ __launch_bounds__(256) void k_gemm_init(
    const float* __restrict__ x, const float* __restrict__ pos,
    const float* __restrict__ Wg, const float* __restrict__ bg,
    const float* __restrict__ Wp, const float* __restrict__ bp,
    float* __restrict__ out, int n)
{
    __shared__ float sWg[D * D];
    __shared__ float sWp[D * D];
    __shared__ float sx[4][D];
    __shared__ float sp[4][D];

    int tid = threadIdx.x;
    for (int i = tid; i < D * D; i += 256) {
        sWg[i] = Wg[i];
        sWp[i] = Wp[i];
    }

    int ln   = tid >> 6;       // local node 0..3
    int col  = tid & 63;       // output column
    int node = blockIdx.x * 4 + ln;

    if (node < n) {
        sx[ln][col] = x[(size_t)node * D + col];
        sp[ln][col] = pos[(size_t)node * D + col];
    }
    __syncthreads();
    if (node >= n) return;

    float ag = 0.f, ap = 0.f;
#pragma unroll
    for (int k = 0; k < D; k++) {
        ag = fmaf(sx[ln][k], sWg[k * D + col], ag);
        ap = fmaf(sp[ln][k], sWp[k * D + col], ap);
    }

    float di = g_dinv[node];
    float hs = ag * di;
    ((float*)g_hs)[(size_t)node * D + col] = hs;
    out[(size_t)node * D + col]  = ap + bp[col] + bg[col] + hs * di;
}

// ---------------------------------------------------------------------------
// K4: edge scatter. 16 threads per edge, one float4 gather each (coalesced
// 256B per edge), 4 scalar atomicAdds into out[dst].
//   out[dst] += hs[src] * dinv[dst]
__global__ __launch_bounds__(256) void k_scatter(
    const void* __restrict__ ei, float* __restrict__ out, int E, int n)
{
    long long idx = (long long)blockIdx.x * blockDim.x + threadIdx.x;
    if (idx >= (long long)E * 16) return;

    int e = (int)(idx >> 4);
    int c = (int)(idx & 15);

    int mode = g_mode;
    int src = edge_at(ei, mode, (size_t)e, n);
    int dst = edge_at(ei, mode, (size_t)E + e, n);

    float w = g_dinv[dst];
    float4 v = g_hs[(size_t)src * 16 + c];

    float* o = out + (size_t)dst * D + c * 4;
    atomicAdd(o + 0, v.x * w);
    atomicAdd(o + 1, v.y * w);
    atomicAdd(o + 2, v.z * w);
    atomicAdd(o + 3, v.w * w);
}

// ---------------------------------------------------------------------------
extern "C" void kernel_launch(void* const* d_in, const int* in_sizes, int n_in,
                              void* d_out, int out_size)
{
    // Identify inputs by size pattern instead of trusting position.
    // Expected: x (N*64), edge_index (2*E), pos (N*64), Wg (64*64), bg (64),
    //           Wp (64*64), bp (64). Same-size inputs keep original order.
    int N = 100000;
    int E = 1600000;
    // Find the edge index: the input whose size is neither N*64, 4096, nor 64.
    int i_edge = 1;
    int feat[2], nf = 0, wmat[2], nw = 0, bias[2], nb = 0;
    for (int i = 0; i < n_in; i++) {
        int s = in_sizes[i];
        if (s == D * D)      { if (nw < 2) wmat[nw++] = i; }
        else if (s == D)     { if (nb < 2) bias[nb++] = i; }
        else if (s % D == 0 && s / D >= 1000) {
            // large node-feature matrix OR edge index (2*E also %64==0)
            // distinguish later by count: exactly two of these are N*64 and
            // one is 2*E. Collect all, resolve below.
            if (nf < 2) feat[nf++] = i; else i_edge = i;
        } else i_edge = i;
    }
    // Resolve: among the three "large" inputs, the standard order is
    // x, edge_index, pos. If we collected 3 larges, the middle one (or the
    // one with a distinct size) is the edge index.
    {
        // gather all large indices in order
        int larges[3], nl = 0;
        for (int i = 0; i < n_in; i++) {
            int s = in_sizes[i];
            if (s != D * D && s != D) larges[nl < 3 ? nl++ : 2] = i;
        }
        if (nl == 3) {
            // if two share a size, the odd one out is edge_index
            int s0 = in_sizes[larges[0]], s1 = in_sizes[larges[1]], s2 = in_sizes[larges[2]];
            int ie;
            if (s0 == s1)      ie = larges[2];
            else if (s0 == s2) ie = larges[1];
            else if (s1 == s2) ie = larges[0];
            else               ie = larges[1];   // fall back: middle position
            i_edge = ie;
            // the remaining two (in order) are x, pos
            int k = 0;
            for (int j = 0; j < 3; j++) if (larges[j] != ie) feat[k++] = larges[j];
            E = in_sizes[ie] / 2;
            N = in_sizes[feat[0]] / D;
        }
    }

    const float* x   = (const float*)d_in[feat[0]];
    const float* pos = (const float*)d_in[feat[1]];
    const void*  ei  = d_in[i_edge];
    const float* Wg  = (const float*)d_in[wmat[0]];
    const float* Wp  = (const float*)d_in[wmat[1]];
    const float* bg  = (const float*)d_in[bias[0]];
    const float* bp  = (const float*)d_in[bias[1]];
    float*       out = (float*)d_out;

    if (N > NMAX) N = NMAX;

    k_detect<<<1, 32>>>(ei, E, N);
    k_zero_deg<<<(N + 255) / 256, 256>>>(N);
    k_degree<<<(E + 255) / 256, 256>>>(ei, E, N);
    k_dinv<<<(N + 255) / 256, 256>>>(N);
    k_gemm_init<<<(N + 3) / 4, 256>>>(x, pos, Wg, bg, Wp, bp, out, N);

    long long total = (long long)E * 16;
    int blocks = (int)((total + 255) / 256);
    k_scatter<<<blocks, 256>>>(ei, out, E, N);
}

// round 4
// speedup vs baseline: 1.4425x; 1.4425x over previous
#include <cuda_runtime.h>
#include <cuda_bf16.h>
#include <cstdint>

#define D      64
#define NMAX   100000
#define EMAX   2000000
#define SCAN_B 1024

// Scratch (allocation-free rule: __device__ globals)
__device__ __align__(16) float4 g_hs[(size_t)NMAX * (D / 4)];  // h * dinv[src]
__device__ float g_dinv[NMAX];
__device__ int   g_deg[NMAX];
__device__ int   g_off[NMAX];      // CSR exclusive offsets
__device__ int   g_cursor[NMAX];   // scan temp, then fill cursors
__device__ int   g_csr[EMAX];      // src per edge, bucketed by dst
__device__ int   g_part[SCAN_B];   // block partial sums
__device__ int   g_partx[SCAN_B];  // exclusive-scanned partials
__device__ int   g_mode;           // 0 = edge_index int64, 1 = int32

// ---------------------------------------------------------------------------
__device__ __forceinline__ int edge_at(const void* ei, int mode, size_t i, int n) {
    long long v;
    if (mode == 0) v = ((const long long*)ei)[i];
    else           v = (long long)((const int*)ei)[i];
    if (v < 0)  v = 0;
    if (v >= n) v = n - 1;
    return (int)v;
}

// K_detect: int64 vs int32, parallel ballot over first 256 values.
__global__ void k_detect(const void* ei, int E, int n) {
    int lane = threadIdx.x;
    const long long* p = (const long long*)ei;
    int lim = E < 256 ? E : 256;
    bool bad = false;
    for (int i = lane; i < lim; i += 32) {
        long long v = p[i];
        if (v < 0 || v >= (long long)n) bad = true;
    }
    unsigned m = __ballot_sync(0xffffffffu, bad);
    if (lane == 0) g_mode = m ? 1 : 0;
}

// K0: zero degree counters
__global__ void k_zero_deg(int n) {
    int i = blockIdx.x * blockDim.x + threadIdx.x;
    if (i < n) g_deg[i] = 0;
}

// K1: degree count over destinations
__global__ void k_degree(const void* __restrict__ ei, int E, int n) {
    int e = blockIdx.x * blockDim.x + threadIdx.x;
    if (e < E) {
        int mode = g_mode;
        int dst = edge_at(ei, mode, (size_t)E + e, n);
        atomicAdd(&g_deg[dst], 1);
    }
}

// ---------------------------------------------------------------------------
// Scan 1: per-block inclusive scan of deg -> g_cursor (temp), block sums -> g_part
__global__ __launch_bounds__(SCAN_B) void k_scan1(int n) {
    __shared__ int s[SCAN_B];
    int t = threadIdx.x;
    int i = blockIdx.x * SCAN_B + t;
    int v = (i < n) ? g_deg[i] : 0;
    s[t] = v;
    __syncthreads();
#pragma unroll
    for (int d = 1; d < SCAN_B; d <<= 1) {
        int u = (t >= d) ? s[t - d] : 0;
        __syncthreads();
        s[t] += u;
        __syncthreads();
    }
    if (i < n) g_cursor[i] = s[t];              // inclusive, block-local
    if (t == SCAN_B - 1) g_part[blockIdx.x] = s[t];
}

// Scan 2: single-block exclusive scan of g_part -> g_partx
__global__ __launch_bounds__(SCAN_B) void k_scan2(int nb) {
    __shared__ int s[SCAN_B];
    int t = threadIdx.x;
    int v = (t < nb) ? g_part[t] : 0;
    s[t] = v;
    __syncthreads();
#pragma unroll
    for (int d = 1; d < SCAN_B; d <<= 1) {
        int u = (t >= d) ? s[t - d] : 0;
        __syncthreads();
        s[t] += u;
        __syncthreads();
    }
    if (t < nb) g_partx[t] = s[t] - v;          // exclusive
}

// Scan 3 + dinv: final exclusive offsets + cursors + dinv
__global__ void k_scan3(int n) {
    int i = blockIdx.x * blockDim.x + threadIdx.x;
    if (i < n) {
        int deg = g_deg[i];
        int o = g_cursor[i] - deg + g_partx[i >> 10];
        g_off[i]    = o;
        g_cursor[i] = o;
        g_dinv[i]   = rsqrtf((float)(deg + 1));
    }
}

// CSR fill: bucket src by dst (int atomics on cursors only)
__global__ void k_fill(const void* __restrict__ ei, int E, int n) {
    int e = blockIdx.x * blockDim.x + threadIdx.x;
    if (e < E) {
        int mode = g_mode;
        int src = edge_at(ei, mode, (size_t)e, n);
        int dst = edge_at(ei, mode, (size_t)E + e, n);
        int p = atomicAdd(&g_cursor[dst], 1);
        if (p < EMAX) g_csr[p] = src;
    }
}

// ---------------------------------------------------------------------------
// GEMM + out init:
//   hs[n]  = (x[n] @ Wg) * dinv[n]
//   out[n] = pos[n] @ Wp + b_pos + b_gcn + hs[n]*dinv[n]   (self-loop)
__global__ __launch_bounds__(256) void k_gemm_init(
    const float* __restrict__ x, const float* __restrict__ pos,
    const float* __restrict__ Wg, const float* __restrict__ bg,
    const float* __restrict__ Wp, const float* __restrict__ bp,
    float* __restrict__ out, int n)
{
    __shared__ float sWg[D * D];
    __shared__ float sWp[D * D];
    __shared__ float sx[4][D];
    __shared__ float sp[4][D];

    int tid = threadIdx.x;
    for (int i = tid; i < D * D; i += 256) {
        sWg[i] = Wg[i];
        sWp[i] = Wp[i];
    }

    int ln   = tid >> 6;
    int col  = tid & 63;
    int node = blockIdx.x * 4 + ln;

    if (node < n) {
        sx[ln][col] = x[(size_t)node * D + col];
        sp[ln][col] = pos[(size_t)node * D + col];
    }
    __syncthreads();
    if (node >= n) return;

    float ag = 0.f, ap = 0.f;
#pragma unroll
    for (int k = 0; k < D; k++) {
        ag = fmaf(sx[ln][k], sWg[k * D + col], ag);
        ap = fmaf(sp[ln][k], sWp[k * D + col], ap);
    }

    float di = g_dinv[node];
    float hs = ag * di;
    ((float*)g_hs)[(size_t)node * D + col] = hs;
    out[(size_t)node * D + col]  = ap + bp[col] + bg[col] + hs * di;
}

// ---------------------------------------------------------------------------
// Aggregate: one warp per node. lane = 2 columns (float2 -> 256B coalesced
// gather per edge). No float atomics: warp owns the node.
//   out[node] += dinv[node] * sum_{src in csr[node]} hs[src]
__global__ __launch_bounds__(256) void k_agg(float* __restrict__ out, int n) {
    int warp = (blockIdx.x * blockDim.x + threadIdx.x) >> 5;
    int lane = threadIdx.x & 31;
    if (warp >= n) return;

    int start = g_off[warp];
    int deg   = g_deg[warp];

    const float2* hs2 = (const float2*)g_hs;
    float ax = 0.f, ay = 0.f;

    int j = 0;
    for (; j + 4 <= deg; j += 4) {
        int s0 = g_csr[start + j + 0];
        int s1 = g_csr[start + j + 1];
        int s2 = g_csr[start + j + 2];
        int s3 = g_csr[start + j + 3];
        float2 v0 = hs2[(size_t)s0 * 32 + lane];
        float2 v1 = hs2[(size_t)s1 * 32 + lane];
        float2 v2 = hs2[(size_t)s2 * 32 + lane];
        float2 v3 = hs2[(size_t)s3 * 32 + lane];
        ax += (v0.x + v1.x) + (v2.x + v3.x);
        ay += (v0.y + v1.y) + (v2.y + v3.y);
    }
    for (; j < deg; j++) {
        int s = g_csr[start + j];
        float2 v = hs2[(size_t)s * 32 + lane];
        ax += v.x;
        ay += v.y;
    }

    float w = g_dinv[warp];
    float2* o = (float2*)out + (size_t)warp * 32 + lane;
    float2 cur = *o;
    cur.x += w * ax;
    cur.y += w * ay;
    *o = cur;
}

// ---------------------------------------------------------------------------
extern "C" void kernel_launch(void* const* d_in, const int* in_sizes, int n_in,
                              void* d_out, int out_size)
{
    // Identify inputs by size pattern (robust to harness reordering).
    int N = 100000, E = 1600000;
    int i_edge = 1;
    int feat[2] = {0, 2}, wmat[2], nw = 0, bias[2], nb = 0;
    for (int i = 0; i < n_in; i++) {
        int s = in_sizes[i];
        if (s == D * D)  { if (nw < 2) wmat[nw++] = i; }
        else if (s == D) { if (nb < 2) bias[nb++] = i; }
    }
    {
        int larges[3], nl = 0;
        for (int i = 0; i < n_in; i++) {
            int s = in_sizes[i];
            if (s != D * D && s != D) { if (nl < 3) larges[nl++] = i; }
        }
        if (nl == 3) {
            int s0 = in_sizes[larges[0]], s1 = in_sizes[larges[1]], s2 = in_sizes[larges[2]];
            int ie;
            if (s0 == s1)      ie = larges[2];
            else if (s0 == s2) ie = larges[1];
            else if (s1 == s2) ie = larges[0];
            else               ie = larges[1];
            i_edge = ie;
            int k = 0;
            for (int j = 0; j < 3; j++) if (larges[j] != ie) feat[k++] = larges[j];
            E = in_sizes[ie] / 2;
            N = in_sizes[feat[0]] / D;
        }
    }

    const float* x   = (const float*)d_in[feat[0]];
    const float* pos = (const float*)d_in[feat[1]];
    const void*  ei  = d_in[i_edge];
    const float* Wg  = (const float*)d_in[wmat[0]];
    const float* Wp  = (const float*)d_in[wmat[1]];
    const float* bg  = (const float*)d_in[bias[0]];
    const float* bp  = (const float*)d_in[bias[1]];
    float*       out = (float*)d_out;

    if (N > NMAX) N = NMAX;
    if (E > EMAX) E = EMAX;

    int nb_scan = (N + SCAN_B - 1) / SCAN_B;

    k_detect<<<1, 32>>>(ei, E, N);
    k_zero_deg<<<(N + 255) / 256, 256>>>(N);
    k_degree<<<(E + 255) / 256, 256>>>(ei, E, N);
    k_scan1<<<nb_scan, SCAN_B>>>(N);
    k_scan2<<<1, SCAN_B>>>(nb_scan);
    k_scan3<<<(N + 255) / 256, 256>>>(N);
    k_fill<<<(E + 255) / 256, 256>>>(ei, E, N);
    k_gemm_init<<<(N + 3) / 4, 256>>>(x, pos, Wg, bg, Wp, bp, out, N);
    k_agg<<<(N * 32 + 255) / 256, 256>>>(out, N);
}

// round 5
// speedup vs baseline: 2.3461x; 1.6264x over previous
#include <cuda_runtime.h>
#include <cuda_bf16.h>
#include <cstdint>

#define D      64
#define NMAX   100000
#define EMAX   2000000
#define SCAN_B 1024

// Scratch (allocation-free rule: __device__ globals)
__device__ __align__(16) float4 g_hs[(size_t)NMAX * (D / 4)];  // h * dinv[src]
__device__ float g_dinv[NMAX];
__device__ int   g_deg[NMAX];
__device__ int   g_off[NMAX];      // CSR exclusive offsets
__device__ int   g_cursor[NMAX];   // scan temp, then fill cursors
__device__ int   g_csr[EMAX];      // src per edge, bucketed by dst
__device__ int   g_part[SCAN_B];   // block partial sums
__device__ int   g_partx[SCAN_B];  // exclusive-scanned partials
__device__ int   g_mode;           // 0 = edge_index int64, 1 = int32

// ---------------------------------------------------------------------------
__device__ __forceinline__ int edge_at(const void* ei, int mode, size_t i, int n) {
    long long v;
    if (mode == 0) v = ((const long long*)ei)[i];
    else           v = (long long)((const int*)ei)[i];
    if (v < 0)  v = 0;
    if (v >= n) v = n - 1;
    return (int)v;
}

// K_init: zero degree counters + dtype detect (block 0, warp 0)
__global__ void k_init(const void* ei, int E, int n) {
    int i = blockIdx.x * blockDim.x + threadIdx.x;
    if (i < n) g_deg[i] = 0;
    if (blockIdx.x == 0 && threadIdx.x < 32) {
        const long long* p = (const long long*)ei;
        int lim = E < 256 ? E : 256;
        bool bad = false;
        for (int k = threadIdx.x; k < lim; k += 32) {
            long long v = p[k];
            if (v < 0 || v >= (long long)n) bad = true;
        }
        unsigned m = __ballot_sync(0xffffffffu, bad);
        if (threadIdx.x == 0) g_mode = m ? 1 : 0;
    }
}

// K1: degree count over destinations
__global__ void k_degree(const void* __restrict__ ei, int E, int n) {
    int e = blockIdx.x * blockDim.x + threadIdx.x;
    if (e < E) {
        int mode = g_mode;
        int dst = edge_at(ei, mode, (size_t)E + e, n);
        atomicAdd(&g_deg[dst], 1);
    }
}

// ---------------------------------------------------------------------------
// Scan 1: per-block inclusive scan of deg -> g_cursor (temp), block sums -> g_part
__global__ __launch_bounds__(SCAN_B) void k_scan1(int n) {
    __shared__ int s[SCAN_B];
    int t = threadIdx.x;
    int i = blockIdx.x * SCAN_B + t;
    int v = (i < n) ? g_deg[i] : 0;
    s[t] = v;
    __syncthreads();
#pragma unroll
    for (int d = 1; d < SCAN_B; d <<= 1) {
        int u = (t >= d) ? s[t - d] : 0;
        __syncthreads();
        s[t] += u;
        __syncthreads();
    }
    if (i < n) g_cursor[i] = s[t];              // inclusive, block-local
    if (t == SCAN_B - 1) g_part[blockIdx.x] = s[t];
}

// Scan 2: single-block exclusive scan of g_part -> g_partx
__global__ __launch_bounds__(SCAN_B) void k_scan2(int nb) {
    __shared__ int s[SCAN_B];
    int t = threadIdx.x;
    int v = (t < nb) ? g_part[t] : 0;
    s[t] = v;
    __syncthreads();
#pragma unroll
    for (int d = 1; d < SCAN_B; d <<= 1) {
        int u = (t >= d) ? s[t - d] : 0;
        __syncthreads();
        s[t] += u;
        __syncthreads();
    }
    if (t < nb) g_partx[t] = s[t] - v;          // exclusive
}

// Scan 3 + dinv: final exclusive offsets + cursors + dinv
__global__ void k_scan3(int n) {
    int i = blockIdx.x * blockDim.x + threadIdx.x;
    if (i < n) {
        int deg = g_deg[i];
        int o = g_cursor[i] - deg + g_partx[i >> 10];
        g_off[i]    = o;
        g_cursor[i] = o;
        g_dinv[i]   = rsqrtf((float)(deg + 1));
    }
}

// CSR fill: bucket src by dst (int atomics on cursors only)
__global__ void k_fill(const void* __restrict__ ei, int E, int n) {
    int e = blockIdx.x * blockDim.x + threadIdx.x;
    if (e < E) {
        int mode = g_mode;
        int src = edge_at(ei, mode, (size_t)e, n);
        int dst = edge_at(ei, mode, (size_t)E + e, n);
        int p = atomicAdd(&g_cursor[dst], 1);
        if (p < EMAX) g_csr[p] = src;
    }
}

// ---------------------------------------------------------------------------
// GEMM + out init. 32 nodes per block (weights loaded once per 32 nodes).
// Thread = (node 0..15, colgroup 0..15); each thread computes a float4 of
// output cols -> LDS.128 weight reads, LDG/STG.128 feature I/O.
//   hs[n]  = (x[n] @ Wg) * dinv[n]
//   out[n] = pos[n] @ Wp + b_pos + b_gcn + hs[n]*dinv[n]   (self-loop)
__global__ __launch_bounds__(256) void k_gemm_init(
    const float* __restrict__ x, const float* __restrict__ pos,
    const float* __restrict__ Wg, const float* __restrict__ bg,
    const float* __restrict__ Wp, const float* __restrict__ bp,
    float* __restrict__ out, int n)
{
    __shared__ float4 sWg[D * 16];   // [k][cg]
    __shared__ float4 sWp[D * 16];
    __shared__ float  sx[16][D];
    __shared__ float  sp[16][D];

    int tid = threadIdx.x;
    const float4* Wg4 = (const float4*)Wg;
    const float4* Wp4 = (const float4*)Wp;
    for (int i = tid; i < D * 16; i += 256) {
        sWg[i] = Wg4[i];
        sWp[i] = Wp4[i];
    }

    int ln = tid >> 4;     // 0..15: local node
    int cg = tid & 15;     // colgroup (4 cols)
    float4 bg4 = ((const float4*)bg)[cg];
    float4 bp4 = ((const float4*)bp)[cg];

    int base = blockIdx.x * 32;
#pragma unroll
    for (int half = 0; half < 2; half++) {
        int gn = base + half * 16 + ln;
        if (gn < n) {
            ((float4*)sx)[ln * 16 + cg] = ((const float4*)x)[(size_t)gn * 16 + cg];
            ((float4*)sp)[ln * 16 + cg] = ((const float4*)pos)[(size_t)gn * 16 + cg];
        }
        __syncthreads();

        if (gn < n) {
            float4 ag = {0.f, 0.f, 0.f, 0.f};
            float4 ap = {0.f, 0.f, 0.f, 0.f};
#pragma unroll
            for (int k = 0; k < D; k++) {
                float xk = sx[ln][k];
                float pk = sp[ln][k];
                float4 wg = sWg[k * 16 + cg];
                float4 wp = sWp[k * 16 + cg];
                ag.x = fmaf(xk, wg.x, ag.x);
                ag.y = fmaf(xk, wg.y, ag.y);
                ag.z = fmaf(xk, wg.z, ag.z);
                ag.w = fmaf(xk, wg.w, ag.w);
                ap.x = fmaf(pk, wp.x, ap.x);
                ap.y = fmaf(pk, wp.y, ap.y);
                ap.z = fmaf(pk, wp.z, ap.z);
                ap.w = fmaf(pk, wp.w, ap.w);
            }
            float di = g_dinv[gn];
            float4 hs = {ag.x * di, ag.y * di, ag.z * di, ag.w * di};
            g_hs[(size_t)gn * 16 + cg] = hs;
            float4 o;
            o.x = ap.x + bp4.x + bg4.x + hs.x * di;
            o.y = ap.y + bp4.y + bg4.y + hs.y * di;
            o.z = ap.z + bp4.z + bg4.z + hs.z * di;
            o.w = ap.w + bp4.w + bg4.w + hs.w * di;
            ((float4*)out)[(size_t)gn * 16 + cg] = o;
        }
        __syncthreads();
    }
}

// ---------------------------------------------------------------------------
// Aggregate: one warp per node, lane = 2 cols (float2 -> 256B coalesced per
// edge). Unroll 8: 8 broadcast index loads then 8 independent gathers (MLP 8).
//   out[node] += dinv[node] * sum_{src in csr[node]} hs[src]
__global__ __launch_bounds__(256) void k_agg(float* __restrict__ out, int n) {
    int warp = (blockIdx.x * blockDim.x + threadIdx.x) >> 5;
    int lane = threadIdx.x & 31;
    if (warp >= n) return;

    int start = g_off[warp];
    int deg   = g_deg[warp];

    const float2* hs2 = (const float2*)g_hs;
    float ax = 0.f, ay = 0.f;

    int j = 0;
    for (; j + 8 <= deg; j += 8) {
        int s[8];
#pragma unroll
        for (int u = 0; u < 8; u++) s[u] = g_csr[start + j + u];
#pragma unroll
        for (int u = 0; u < 8; u++) {
            float2 v = hs2[(size_t)s[u] * 32 + lane];
            ax += v.x;
            ay += v.y;
        }
    }
    for (; j < deg; j++) {
        int sj = g_csr[start + j];
        float2 v = hs2[(size_t)sj * 32 + lane];
        ax += v.x;
        ay += v.y;
    }

    float w = g_dinv[warp];
    float2* o = (float2*)out + (size_t)warp * 32 + lane;
    float2 cur = *o;
    cur.x += w * ax;
    cur.y += w * ay;
    *o = cur;
}

// ---------------------------------------------------------------------------
extern "C" void kernel_launch(void* const* d_in, const int* in_sizes, int n_in,
                              void* d_out, int out_size)
{
    // Identify inputs by size pattern (robust to harness reordering).
    int N = 100000, E = 1600000;
    int i_edge = 1;
    int feat[2] = {0, 2}, wmat[2], nw = 0, bias[2], nb = 0;
    for (int i = 0; i < n_in; i++) {
        int s = in_sizes[i];
        if (s == D * D)  { if (nw < 2) wmat[nw++] = i; }
        else if (s == D) { if (nb < 2) bias[nb++] = i; }
    }
    {
        int larges[3], nl = 0;
        for (int i = 0; i < n_in; i++) {
            int s = in_sizes[i];
            if (s != D * D && s != D) { if (nl < 3) larges[nl++] = i; }
        }
        if (nl == 3) {
            int s0 = in_sizes[larges[0]], s1 = in_sizes[larges[1]], s2 = in_sizes[larges[2]];
            int ie;
            if (s0 == s1)      ie = larges[2];
            else if (s0 == s2) ie = larges[1];
            else if (s1 == s2) ie = larges[0];
            else               ie = larges[1];
            i_edge = ie;
            int k = 0;
            for (int j = 0; j < 3; j++) if (larges[j] != ie) feat[k++] = larges[j];
            E = in_sizes[ie] / 2;
            N = in_sizes[feat[0]] / D;
        }
    }

    const float* x   = (const float*)d_in[feat[0]];
    const float* pos = (const float*)d_in[feat[1]];
    const void*  ei  = d_in[i_edge];
    const float* Wg  = (const float*)d_in[wmat[0]];
    const float* Wp  = (const float*)d_in[wmat[1]];
    const float* bg  = (const float*)d_in[bias[0]];
    const float* bp  = (const float*)d_in[bias[1]];
    float*       out = (float*)d_out;

    if (N > NMAX) N = NMAX;
    if (E > EMAX) E = EMAX;

    int nb_scan = (N + SCAN_B - 1) / SCAN_B;

    k_init<<<(N + 255) / 256, 256>>>(ei, E, N);
    k_degree<<<(E + 255) / 256, 256>>>(ei, E, N);
    k_scan1<<<nb_scan, SCAN_B>>>(N);
    k_scan2<<<1, SCAN_B>>>(nb_scan);
    k_scan3<<<(N + 255) / 256, 256>>>(N);
    k_fill<<<(E + 255) / 256, 256>>>(ei, E, N);
    k_gemm_init<<<(N + 31) / 32, 256>>>(x, pos, Wg, bg, Wp, bp, out, N);
    k_agg<<<(N * 32 + 255) / 256, 256>>>(out, N);
}